// round 16
// baseline (speedup 1.0000x reference)
#include <cuda_runtime.h>
#include <cuda_fp16.h>
#include <cstdint>

// -------------------- problem constants --------------------
#define B_SZ 4096
#define I_SZ 1024
#define H_SZ 2048
#define NSTEPS 5
#define DT_C 0.1f

// -------------------- GEMM tiling (frozen R13 body) --------------------
#define BM 128
#define BN 256
#define BK 32                 // 32 halves per k-tile = 64B rows
#define NSTAGE 4
#define THREADS 256

#define SA_BYTES (BM * 64)                    // 8192
#define SB_BYTES (BN * 64)                    // 16384
#define STAGE_BYTES (SA_BYTES + SB_BYTES)     // 24576
#define SMEM_TOTAL (NSTAGE * STAGE_BYTES)     // 98304

// -------------------- scratch --------------------
__device__ __half g_C1h[B_SZ * H_SZ];
__device__ __half g_C2h[B_SZ * H_SZ];
__device__ __half g_G1h[B_SZ * H_SZ];
__device__ __half g_G2h[B_SZ * H_SZ];
__device__ __half g_h16  [B_SZ * H_SZ];
__device__ __half g_x16  [B_SZ * I_SZ];
__device__ __half g_Wrec16[H_SZ * H_SZ];
__device__ __half g_tauh16[H_SZ * H_SZ];
__device__ __half g_Win16 [H_SZ * I_SZ];
__device__ __half g_taux16[H_SZ * I_SZ];

// -------------------- PTX helpers --------------------
__device__ __forceinline__ void cp16(uint32_t smem, const void* g) {
    asm volatile("cp.async.cg.shared.global [%0], [%1], 16;" :: "r"(smem), "l"(g) : "memory");
}
__device__ __forceinline__ void cp_commit() {
    asm volatile("cp.async.commit_group;" ::: "memory");
}
template <int N>
__device__ __forceinline__ void cp_wait() {
    asm volatile("cp.async.wait_group %0;" :: "n"(N) : "memory");
}
__device__ __forceinline__ void ldsm4(uint32_t* r, uint32_t a) {
    asm volatile("ldmatrix.sync.aligned.m8n8.x4.shared.b16 {%0,%1,%2,%3}, [%4];"
                 : "=r"(r[0]), "=r"(r[1]), "=r"(r[2]), "=r"(r[3]) : "r"(a));
}
__device__ __forceinline__ void mma_f16(float* d, const uint32_t* a, const uint32_t* b) {
    asm volatile(
        "mma.sync.aligned.m16n8k16.row.col.f32.f16.f16.f32 "
        "{%0,%1,%2,%3}, {%4,%5,%6,%7}, {%8,%9}, {%0,%1,%2,%3};"
        : "+f"(d[0]), "+f"(d[1]), "+f"(d[2]), "+f"(d[3])
        : "r"(a[0]), "r"(a[1]), "r"(a[2]), "r"(a[3]), "r"(b[0]), "r"(b[1]));
}
__device__ __forceinline__ uint32_t swadr(uint32_t base, int r, int g) {
    const int c = g ^ (r & 3) ^ ((r >> 2) & 1);
    return base + (uint32_t)(r * 64 + c * 16);
}
__device__ __forceinline__ float4 h4_to_f4(uint2 u) {
    const __half2 a = *(__half2*)&u.x;
    const __half2 b = *(__half2*)&u.y;
    const float2 fa = __half22float2(a);
    const float2 fb = __half22float2(b);
    return make_float4(fa.x, fa.y, fb.x, fb.y);
}

// -------------------- fused fp32 -> fp16 convert --------------------
struct CvtJob { const float* s; __half* d; int rows, cols, sld, dld; };
struct CvtJobs { CvtJob j[6]; };

__global__ void cvt_all_kernel(CvtJobs J)
{
    const CvtJob job = J.j[blockIdx.y];
    const int per_row = job.cols >> 3;
    const long total = (long)job.rows * per_row;
    for (long i = (long)blockIdx.x * blockDim.x + threadIdx.x; i < total;
         i += (long)gridDim.x * blockDim.x) {
        const int r = (int)(i / per_row);
        const int c = (int)(i % per_row) << 3;
        const float4 a = *(const float4*)(job.s + (long)r * job.sld + c);
        const float4 b = *(const float4*)(job.s + (long)r * job.sld + c + 4);
        __half2 h0 = __float22half2_rn(make_float2(a.x, a.y));
        __half2 h1 = __float22half2_rn(make_float2(a.z, a.w));
        __half2 h2 = __float22half2_rn(make_float2(b.x, b.y));
        __half2 h3 = __float22half2_rn(make_float2(b.z, b.w));
        uint4 u;
        u.x = *(uint32_t*)&h0; u.y = *(uint32_t*)&h1;
        u.z = *(uint32_t*)&h2; u.w = *(uint32_t*)&h3;
        *(uint4*)(job.d + (long)r * job.dld + c) = u;
    }
}

// -------------------- dual-B fp16 GEMM (R13 body) + optional elem-add ------
// Each job: two GEMMs (B0->C0, B1->C1) over the full [M, H_SZ] output.
// Optional per-half addend array (same [M, H_SZ] shape) folded in epilogue:
//   C_half = A@B_half^T (+ bias_half[col]) (+ add_half[row,col])
// grid.x = 16 (one job) or 32 (two jobs, job = blockIdx.x >> 4).
struct GemmJob {
    const __half *A; int lda;
    const __half *B0; int ldb0; __half *C0; const float *bias0; const __half *add0;
    const __half *B1; int ldb1; __half *C1; const float *bias1; const __half *add1;
    int K;
};

__global__ void __launch_bounds__(THREADS, 1)
gemm_dual_f16(GemmJob j0, GemmJob j1)
{
    extern __shared__ __align__(1024) char smem[];
    const uint32_t sb = (uint32_t)__cvta_generic_to_shared(smem);

    const int tid  = threadIdx.x;
    const int lane = tid & 31;
    const int wid  = tid >> 5;
    const int wm   = (wid >> 2) * 64;
    const int wn   = (wid & 3) * 64;

    const GemmJob jb = (blockIdx.x >> 4) ? j1 : j0;
    const int half_ = (blockIdx.x >> 3) & 1;
    const int nblk  = blockIdx.x & 7;
    const int m0 = blockIdx.y * BM;
    const int n0 = nblk * BN;

    const __half* A    = jb.A;
    const int     lda  = jb.lda;
    const __half* Bw   = half_ ? jb.B1 : jb.B0;
    const int     ldb  = half_ ? jb.ldb1 : jb.ldb0;
    __half*       C    = half_ ? jb.C1 : jb.C0;
    const float*  bias = half_ ? jb.bias1 : jb.bias0;
    const __half* addp = half_ ? jb.add1 : jb.add0;
    const int     K    = jb.K;

    const int lr = tid >> 2;
    const int lg = tid & 3;
    const __half* gA = A  + (long)(m0 + lr) * lda + lg * 8;
    const __half* gB = Bw + (long)(n0 + lr) * ldb + lg * 8;
    const long strideA64 = (long)64 * lda;
    const long strideB64 = (long)64 * ldb;

    const int arow = (lane & 7) + ((lane >> 3) & 1) * 8;
    const int agof = (lane >> 4);
    const int brow = (lane & 7) + ((lane >> 4) & 1) * 8;
    const int bgof = (lane >> 3) & 1;

    float acc[4][8][4];
#pragma unroll
    for (int mt = 0; mt < 4; mt++)
#pragma unroll
        for (int nt = 0; nt < 8; nt++)
#pragma unroll
            for (int r = 0; r < 4; r++) acc[mt][nt][r] = 0.f;

    const int nK = K / BK;

    auto load_stage = [&](int s, int kt) {
        const uint32_t sA = sb + s * STAGE_BYTES;
        const uint32_t sB = sA + SA_BYTES;
        const int koff = kt * BK;
        cp16(swadr(sA, lr,       lg), gA + koff);
        cp16(swadr(sA, lr + 64,  lg), gA + koff + strideA64);
        cp16(swadr(sB, lr,       lg), gB + koff);
        cp16(swadr(sB, lr + 64,  lg), gB + koff + strideB64);
        cp16(swadr(sB, lr + 128, lg), gB + koff + 2 * strideB64);
        cp16(swadr(sB, lr + 192, lg), gB + koff + 3 * strideB64);
    };

#pragma unroll
    for (int s = 0; s < NSTAGE - 1; s++) {
        load_stage(s, s);
        cp_commit();
    }

    for (int kt = 0; kt < nK; kt++) {
        cp_wait<NSTAGE - 2>();
        __syncthreads();

        const int kload = kt + NSTAGE - 1;
        if (kload < nK) load_stage(kload & (NSTAGE - 1), kload);
        cp_commit();

        const uint32_t sA = sb + (kt & (NSTAGE - 1)) * STAGE_BYTES;
        const uint32_t sB = sA + SA_BYTES;

#pragma unroll
        for (int ks = 0; ks < 2; ks++) {
            uint32_t af[4][4], bf[4][4];
#pragma unroll
            for (int mt = 0; mt < 4; mt++)
                ldsm4(af[mt], swadr(sA, wm + mt * 16 + arow, 2 * ks + agof));
#pragma unroll
            for (int p = 0; p < 4; p++)
                ldsm4(bf[p], swadr(sB, wn + p * 16 + brow, 2 * ks + bgof));
#pragma unroll
            for (int mt = 0; mt < 4; mt++)
#pragma unroll
                for (int p = 0; p < 4; p++) {
                    mma_f16(acc[mt][2 * p],     af[mt], &bf[p][0]);
                    mma_f16(acc[mt][2 * p + 1], af[mt], &bf[p][2]);
                }
        }
    }

    // ---- epilogue: fp16 stores (+bias[col], +add[row,col]) ----
    const int grp = lane >> 2;
    const int tig = lane & 3;
#pragma unroll
    for (int mt = 0; mt < 4; mt++) {
        const int row0 = m0 + wm + mt * 16 + grp;
#pragma unroll
        for (int nt = 0; nt < 8; nt++) {
            const int col = n0 + wn + nt * 8 + 2 * tig;
            const long off0 = (long)row0 * H_SZ + col;
            const long off1 = (long)(row0 + 8) * H_SZ + col;
            float v00 = acc[mt][nt][0], v01 = acc[mt][nt][1];
            float v10 = acc[mt][nt][2], v11 = acc[mt][nt][3];
            if (bias) {
                const float b0 = __ldg(bias + col), b1 = __ldg(bias + col + 1);
                v00 += b0; v01 += b1; v10 += b0; v11 += b1;
            }
            if (addp) {
                const float2 a0 = __half22float2(*(const __half2*)(addp + off0));
                const float2 a1 = __half22float2(*(const __half2*)(addp + off1));
                v00 += a0.x; v01 += a0.y; v10 += a1.x; v11 += a1.y;
            }
            *(__half2*)(C + off0) = __floats2half2_rn(v00, v01);
            *(__half2*)(C + off1) = __floats2half2_rn(v10, v11);
        }
    }
}

// -------------------- elementwise liquid step (fp16 state, in place) -------
// FOLDED=1: G1 already contains +C2, G2 already contains +C1 (3-array reads).
// FOLDED=0: reads C1/C2 explicitly (step 0, where fold would race the inv job).
template <int FOLDED>
__global__ void __launch_bounds__(256)
liquid_step_kernel(__half* __restrict__ h16,
                   const __half* __restrict__ G1,
                   const __half* __restrict__ G2,
                   const __half* __restrict__ C1,
                   const __half* __restrict__ C2,
                   const float* __restrict__ tau_base,
                   float* __restrict__ h_out,
                   float* __restrict__ tau_out)
{
    const int idx = (blockIdx.x * 256 + threadIdx.x) * 4;
    const int j = idx & (H_SZ - 1);

    float4 g1 = h4_to_f4(*(const uint2*)(G1 + idx));
    float4 g2 = h4_to_f4(*(const uint2*)(G2 + idx));
    float4 c1, c2;
    if (!FOLDED) {
        c1 = h4_to_f4(*(const uint2*)(C1 + idx));
        c2 = h4_to_f4(*(const uint2*)(C2 + idx));
    }
    float4 hv = h4_to_f4(*(const uint2*)(h16 + idx));
    float4 tb = *(const float4*)(tau_base + j);

    float4 hn, tv;
#define ONE_LANE(f)                                                        \
    {                                                                      \
        float tl  = FOLDED ? g1.f : (c2.f + g1.f);                         \
        float pre = FOLDED ? g2.f : (c1.f + g2.f);                         \
        float sg  = 1.f / (1.f + expf(-tl));                               \
        float tau = tb.f * (0.5f + sg);                                    \
        float act = tanhf(pre);                                            \
        hn.f = hv.f + DT_C * (act - hv.f) / tau;                           \
        tv.f = tau;                                                        \
    }
    ONE_LANE(x) ONE_LANE(y) ONE_LANE(z) ONE_LANE(w)
#undef ONE_LANE

    __half2 p0 = __float22half2_rn(make_float2(hn.x, hn.y));
    __half2 p1 = __float22half2_rn(make_float2(hn.z, hn.w));
    uint2 u; u.x = *(uint32_t*)&p0; u.y = *(uint32_t*)&p1;
    *(uint2*)(h16 + idx) = u;

    if (h_out)   *(float4*)(h_out + idx)   = hn;
    if (tau_out) *(float4*)(tau_out + idx) = tv;
}

// -------------------- launcher --------------------
extern "C" void kernel_launch(void* const* d_in, const int* in_sizes, int n_in,
                              void* d_out, int out_size)
{
    (void)in_sizes; (void)n_in; (void)out_size;

    const float* x           = (const float*)d_in[0];
    const float* hidden      = (const float*)d_in[1];
    const float* W_rec       = (const float*)d_in[2];
    const float* W_in_w      = (const float*)d_in[3];
    const float* W_in_b      = (const float*)d_in[4];
    const float* tau_base    = (const float*)d_in[5];
    const float* tau_adapt_w = (const float*)d_in[6];
    const float* tau_adapt_b = (const float*)d_in[7];

    float* out_h   = (float*)d_out;
    float* out_tau = out_h + (long)B_SZ * H_SZ;

    __half *C1h, *C2h, *G1h, *G2h, *x16, *h16, *Wrec16, *tauh16, *Win16, *taux16;
    cudaGetSymbolAddress((void**)&C1h,    g_C1h);
    cudaGetSymbolAddress((void**)&C2h,    g_C2h);
    cudaGetSymbolAddress((void**)&G1h,    g_G1h);
    cudaGetSymbolAddress((void**)&G2h,    g_G2h);
    cudaGetSymbolAddress((void**)&x16,    g_x16);
    cudaGetSymbolAddress((void**)&h16,    g_h16);
    cudaGetSymbolAddress((void**)&Wrec16, g_Wrec16);
    cudaGetSymbolAddress((void**)&tauh16, g_tauh16);
    cudaGetSymbolAddress((void**)&Win16,  g_Win16);
    cudaGetSymbolAddress((void**)&taux16, g_taux16);

    cudaFuncSetAttribute(gemm_dual_f16, cudaFuncAttributeMaxDynamicSharedMemorySize, SMEM_TOTAL);

    const int ldtau = I_SZ + H_SZ;     // 3072

    // ---- one fused conversion launch ----
    CvtJobs J;
    J.j[0] = {x,                  x16,    B_SZ, I_SZ, I_SZ,  I_SZ};
    J.j[1] = {hidden,             h16,    B_SZ, H_SZ, H_SZ,  H_SZ};
    J.j[2] = {W_rec,              Wrec16, H_SZ, H_SZ, H_SZ,  H_SZ};
    J.j[3] = {tau_adapt_w + I_SZ, tauh16, H_SZ, H_SZ, ldtau, H_SZ};
    J.j[4] = {W_in_w,             Win16,  H_SZ, I_SZ, I_SZ,  I_SZ};
    J.j[5] = {tau_adapt_w,        taux16, H_SZ, I_SZ, ldtau, I_SZ};
    cvt_all_kernel<<<dim3(128, 6), 256>>>(J);

    // ---- merged launch: invariant GEMMs (job0) + step-0 GEMMs (job1) ----
    // step-0 GEMMs must NOT fold C1/C2 (written concurrently by job0).
    GemmJob inv   = { x16, I_SZ,
                      Win16,  I_SZ, C1h, W_in_b,      nullptr,
                      taux16, I_SZ, C2h, tau_adapt_b, nullptr,
                      I_SZ };
    GemmJob loop0 = { h16, H_SZ,
                      tauh16, H_SZ, G1h, nullptr, nullptr,
                      Wrec16, H_SZ, G2h, nullptr, nullptr,
                      H_SZ };
    // folded loop job (steps 1-4): G1' = h@tau_h^T + C2, G2' = h@W_rec^T + C1
    GemmJob loopF = { h16, H_SZ,
                      tauh16, H_SZ, G1h, nullptr, C2h,
                      Wrec16, H_SZ, G2h, nullptr, C1h,
                      H_SZ };

    gemm_dual_f16<<<dim3(32, B_SZ / BM), THREADS, SMEM_TOTAL>>>(inv, loop0);

    const int n_ew = (B_SZ * H_SZ) / 4 / 256;
    for (int s = 0; s < NSTEPS; s++) {
        if (s > 0)
            gemm_dual_f16<<<dim3(16, B_SZ / BM), THREADS, SMEM_TOTAL>>>(loopF, loopF);

        float* ho = (s == NSTEPS - 1) ? out_h   : nullptr;
        float* to = (s == NSTEPS - 1) ? out_tau : nullptr;
        if (s == 0)
            liquid_step_kernel<0><<<n_ew, 256>>>(h16, G1h, G2h, C1h, C2h, tau_base, ho, to);
        else
            liquid_step_kernel<1><<<n_ew, 256>>>(h16, G1h, G2h, nullptr, nullptr, tau_base, ho, to);
    }
}

// round 17
// speedup vs baseline: 1.0681x; 1.0681x over previous
#include <cuda_runtime.h>
#include <cuda_fp16.h>
#include <cstdint>

// -------------------- problem constants --------------------
#define B_SZ 4096
#define I_SZ 1024
#define H_SZ 2048
#define NSTEPS 5
#define DT_C 0.1f

// -------------------- GEMM tiling (frozen R13 body) --------------------
#define BM 128
#define BN 256
#define BK 32                 // 32 halves per k-tile = 64B rows
#define NSTAGE 4
#define THREADS 256

#define SA_BYTES (BM * 64)                    // 8192
#define SB_BYTES (BN * 64)                    // 16384
#define STAGE_BYTES (SA_BYTES + SB_BYTES)     // 24576
#define SMEM_TOTAL (NSTAGE * STAGE_BYTES)     // 98304

// -------------------- scratch --------------------
__device__ __half g_C1h[B_SZ * H_SZ];
__device__ __half g_C2h[B_SZ * H_SZ];
__device__ __half g_G1h[B_SZ * H_SZ];
__device__ __half g_G2h[B_SZ * H_SZ];
__device__ __half g_h16  [B_SZ * H_SZ];
__device__ __half g_x16  [B_SZ * I_SZ];
__device__ __half g_Wrec16[H_SZ * H_SZ];
__device__ __half g_tauh16[H_SZ * H_SZ];
__device__ __half g_Win16 [H_SZ * I_SZ];
__device__ __half g_taux16[H_SZ * I_SZ];

// -------------------- PTX helpers --------------------
__device__ __forceinline__ void cp16(uint32_t smem, const void* g) {
    asm volatile("cp.async.cg.shared.global [%0], [%1], 16;" :: "r"(smem), "l"(g) : "memory");
}
__device__ __forceinline__ void cp_commit() {
    asm volatile("cp.async.commit_group;" ::: "memory");
}
template <int N>
__device__ __forceinline__ void cp_wait() {
    asm volatile("cp.async.wait_group %0;" :: "n"(N) : "memory");
}
__device__ __forceinline__ void ldsm4(uint32_t* r, uint32_t a) {
    asm volatile("ldmatrix.sync.aligned.m8n8.x4.shared.b16 {%0,%1,%2,%3}, [%4];"
                 : "=r"(r[0]), "=r"(r[1]), "=r"(r[2]), "=r"(r[3]) : "r"(a));
}
__device__ __forceinline__ void mma_f16(float* d, const uint32_t* a, const uint32_t* b) {
    asm volatile(
        "mma.sync.aligned.m16n8k16.row.col.f32.f16.f16.f32 "
        "{%0,%1,%2,%3}, {%4,%5,%6,%7}, {%8,%9}, {%0,%1,%2,%3};"
        : "+f"(d[0]), "+f"(d[1]), "+f"(d[2]), "+f"(d[3])
        : "r"(a[0]), "r"(a[1]), "r"(a[2]), "r"(a[3]), "r"(b[0]), "r"(b[1]));
}
__device__ __forceinline__ uint32_t swadr(uint32_t base, int r, int g) {
    const int c = g ^ (r & 3) ^ ((r >> 2) & 1);
    return base + (uint32_t)(r * 64 + c * 16);
}

// -------------------- fused fp32 -> fp16 convert --------------------
struct CvtJob { const float* s; __half* d; int rows, cols, sld, dld; };
struct CvtJobs { CvtJob j[6]; };

__global__ void cvt_all_kernel(CvtJobs J)
{
    const CvtJob job = J.j[blockIdx.y];
    const int per_row = job.cols >> 3;
    const long total = (long)job.rows * per_row;
    for (long i = (long)blockIdx.x * blockDim.x + threadIdx.x; i < total;
         i += (long)gridDim.x * blockDim.x) {
        const int r = (int)(i / per_row);
        const int c = (int)(i % per_row) << 3;
        const float4 a = *(const float4*)(job.s + (long)r * job.sld + c);
        const float4 b = *(const float4*)(job.s + (long)r * job.sld + c + 4);
        __half2 h0 = __float22half2_rn(make_float2(a.x, a.y));
        __half2 h1 = __float22half2_rn(make_float2(a.z, a.w));
        __half2 h2 = __float22half2_rn(make_float2(b.x, b.y));
        __half2 h3 = __float22half2_rn(make_float2(b.z, b.w));
        uint4 u;
        u.x = *(uint32_t*)&h0; u.y = *(uint32_t*)&h1;
        u.z = *(uint32_t*)&h2; u.w = *(uint32_t*)&h3;
        *(uint4*)(job.d + (long)r * job.dld + c) = u;
    }
}

// -------------------- dual-B fp16 GEMM (R13 body), job-table ----------------
struct GemmJob {
    const __half *A; int lda;
    const __half *B0; int ldb0; __half *C0; const float *bias0;
    const __half *B1; int ldb1; __half *C1; const float *bias1;
    int K;
};

__global__ void __launch_bounds__(THREADS, 1)
gemm_dual_f16(GemmJob j0, GemmJob j1)
{
    extern __shared__ __align__(1024) char smem[];
    const uint32_t sb = (uint32_t)__cvta_generic_to_shared(smem);

    const int tid  = threadIdx.x;
    const int lane = tid & 31;
    const int wid  = tid >> 5;
    const int wm   = (wid >> 2) * 64;
    const int wn   = (wid & 3) * 64;

    const GemmJob jb = (blockIdx.x >> 4) ? j1 : j0;
    const int half_ = (blockIdx.x >> 3) & 1;
    const int nblk  = blockIdx.x & 7;
    const int m0 = blockIdx.y * BM;
    const int n0 = nblk * BN;

    const __half* A    = jb.A;
    const int     lda  = jb.lda;
    const __half* Bw   = half_ ? jb.B1 : jb.B0;
    const int     ldb  = half_ ? jb.ldb1 : jb.ldb0;
    __half*       C    = half_ ? jb.C1 : jb.C0;
    const float*  bias = half_ ? jb.bias1 : jb.bias0;
    const int     K    = jb.K;

    const int lr = tid >> 2;
    const int lg = tid & 3;
    const __half* gA = A  + (long)(m0 + lr) * lda + lg * 8;
    const __half* gB = Bw + (long)(n0 + lr) * ldb + lg * 8;
    const long strideA64 = (long)64 * lda;
    const long strideB64 = (long)64 * ldb;

    const int arow = (lane & 7) + ((lane >> 3) & 1) * 8;
    const int agof = (lane >> 4);
    const int brow = (lane & 7) + ((lane >> 4) & 1) * 8;
    const int bgof = (lane >> 3) & 1;

    float acc[4][8][4];
#pragma unroll
    for (int mt = 0; mt < 4; mt++)
#pragma unroll
        for (int nt = 0; nt < 8; nt++)
#pragma unroll
            for (int r = 0; r < 4; r++) acc[mt][nt][r] = 0.f;

    const int nK = K / BK;

    auto load_stage = [&](int s, int kt) {
        const uint32_t sA = sb + s * STAGE_BYTES;
        const uint32_t sB = sA + SA_BYTES;
        const int koff = kt * BK;
        cp16(swadr(sA, lr,       lg), gA + koff);
        cp16(swadr(sA, lr + 64,  lg), gA + koff + strideA64);
        cp16(swadr(sB, lr,       lg), gB + koff);
        cp16(swadr(sB, lr + 64,  lg), gB + koff + strideB64);
        cp16(swadr(sB, lr + 128, lg), gB + koff + 2 * strideB64);
        cp16(swadr(sB, lr + 192, lg), gB + koff + 3 * strideB64);
    };

#pragma unroll
    for (int s = 0; s < NSTAGE - 1; s++) {
        load_stage(s, s);
        cp_commit();
    }

    for (int kt = 0; kt < nK; kt++) {
        cp_wait<NSTAGE - 2>();
        __syncthreads();

        const int kload = kt + NSTAGE - 1;
        if (kload < nK) load_stage(kload & (NSTAGE - 1), kload);
        cp_commit();

        const uint32_t sA = sb + (kt & (NSTAGE - 1)) * STAGE_BYTES;
        const uint32_t sB = sA + SA_BYTES;

#pragma unroll
        for (int ks = 0; ks < 2; ks++) {
            uint32_t af[4][4], bf[4][4];
#pragma unroll
            for (int mt = 0; mt < 4; mt++)
                ldsm4(af[mt], swadr(sA, wm + mt * 16 + arow, 2 * ks + agof));
#pragma unroll
            for (int p = 0; p < 4; p++)
                ldsm4(bf[p], swadr(sB, wn + p * 16 + brow, 2 * ks + bgof));
#pragma unroll
            for (int mt = 0; mt < 4; mt++)
#pragma unroll
                for (int p = 0; p < 4; p++) {
                    mma_f16(acc[mt][2 * p],     af[mt], &bf[p][0]);
                    mma_f16(acc[mt][2 * p + 1], af[mt], &bf[p][2]);
                }
        }
    }

    // ---- epilogue: fp16 stores ----
    const int grp = lane >> 2;
    const int tig = lane & 3;
#pragma unroll
    for (int mt = 0; mt < 4; mt++) {
        const int row0 = m0 + wm + mt * 16 + grp;
#pragma unroll
        for (int nt = 0; nt < 8; nt++) {
            const int col = n0 + wn + nt * 8 + 2 * tig;
            float b0 = 0.f, b1 = 0.f;
            if (bias) { b0 = __ldg(bias + col); b1 = __ldg(bias + col + 1); }
            __half2 p0 = __floats2half2_rn(acc[mt][nt][0] + b0, acc[mt][nt][1] + b1);
            __half2 p1 = __floats2half2_rn(acc[mt][nt][2] + b0, acc[mt][nt][3] + b1);
            *(__half2*)(C + (long)row0 * H_SZ + col)       = p0;
            *(__half2*)(C + (long)(row0 + 8) * H_SZ + col) = p1;
        }
    }
}

// -------------------- elementwise liquid step (fp16 state, 16B accesses) ---
__global__ void __launch_bounds__(256)
liquid_step_kernel(__half* __restrict__ h16,
                   const __half* __restrict__ G1,
                   const __half* __restrict__ G2,
                   const __half* __restrict__ C1,
                   const __half* __restrict__ C2,
                   const float* __restrict__ tau_base,
                   float* __restrict__ h_out,
                   float* __restrict__ tau_out)
{
    const int idx = (blockIdx.x * 256 + threadIdx.x) * 8;   // 8 halves = 16B
    const int j = idx & (H_SZ - 1);

    const uint4 ug1 = *(const uint4*)(G1 + idx);
    const uint4 ug2 = *(const uint4*)(G2 + idx);
    const uint4 uc1 = *(const uint4*)(C1 + idx);
    const uint4 uc2 = *(const uint4*)(C2 + idx);
    const uint4 uhv = *(const uint4*)(h16 + idx);
    const float4 tb0 = *(const float4*)(tau_base + j);
    const float4 tb1 = *(const float4*)(tau_base + j + 4);

    uint4 uout;
    float4 hn0, hn1, tv0, tv1;

#define LANE2(w, hnf, tvf, tbf, p)                                          \
    {                                                                       \
        const float2 g1 = __half22float2(*(const __half2*)&ug1.w);          \
        const float2 g2 = __half22float2(*(const __half2*)&ug2.w);          \
        const float2 c1 = __half22float2(*(const __half2*)&uc1.w);          \
        const float2 c2 = __half22float2(*(const __half2*)&uc2.w);          \
        const float2 hv = __half22float2(*(const __half2*)&uhv.w);          \
        float2 hn, tv;                                                      \
        {                                                                   \
            const float sg  = 1.f / (1.f + expf(-(c2.x + g1.x)));           \
            const float tau = tbf.p * (0.5f + sg);                          \
            const float act = tanhf(g2.x + c1.x);                           \
            hn.x = hv.x + DT_C * (act - hv.x) / tau;  tv.x = tau;           \
        }                                                                   \
        {                                                                   \
            const float sg  = 1.f / (1.f + expf(-(c2.y + g1.y)));           \
            const float tau = tbf.p##2 * (0.5f + sg);                       \
            const float act = tanhf(g2.y + c1.y);                           \
            hn.y = hv.y + DT_C * (act - hv.y) / tau;  tv.y = tau;           \
        }                                                                   \
        __half2 ph = __float22half2_rn(hn);                                 \
        uout.w = *(uint32_t*)&ph;                                           \
        hnf = hn; tvf = tv;                                                 \
    }

    float2 hA, hB, hC, hD, tA, tB, tC, tD;
    // expand manually (macro trick for tau pairs): tb0 = {x,y,z,w} covers lanes 0-3
    {
        const float2 g1 = __half22float2(*(const __half2*)&ug1.x);
        const float2 g2 = __half22float2(*(const __half2*)&ug2.x);
        const float2 c1 = __half22float2(*(const __half2*)&uc1.x);
        const float2 c2 = __half22float2(*(const __half2*)&uc2.x);
        const float2 hv = __half22float2(*(const __half2*)&uhv.x);
        float sg = 1.f / (1.f + expf(-(c2.x + g1.x)));
        float tau = tb0.x * (0.5f + sg);
        hA.x = hv.x + DT_C * (tanhf(g2.x + c1.x) - hv.x) / tau; tA.x = tau;
        sg = 1.f / (1.f + expf(-(c2.y + g1.y)));
        tau = tb0.y * (0.5f + sg);
        hA.y = hv.y + DT_C * (tanhf(g2.y + c1.y) - hv.y) / tau; tA.y = tau;
        __half2 ph = __float22half2_rn(hA); uout.x = *(uint32_t*)&ph;
    }
    {
        const float2 g1 = __half22float2(*(const __half2*)&ug1.y);
        const float2 g2 = __half22float2(*(const __half2*)&ug2.y);
        const float2 c1 = __half22float2(*(const __half2*)&uc1.y);
        const float2 c2 = __half22float2(*(const __half2*)&uc2.y);
        const float2 hv = __half22float2(*(const __half2*)&uhv.y);
        float sg = 1.f / (1.f + expf(-(c2.x + g1.x)));
        float tau = tb0.z * (0.5f + sg);
        hB.x = hv.x + DT_C * (tanhf(g2.x + c1.x) - hv.x) / tau; tB.x = tau;
        sg = 1.f / (1.f + expf(-(c2.y + g1.y)));
        tau = tb0.w * (0.5f + sg);
        hB.y = hv.y + DT_C * (tanhf(g2.y + c1.y) - hv.y) / tau; tB.y = tau;
        __half2 ph = __float22half2_rn(hB); uout.y = *(uint32_t*)&ph;
    }
    {
        const float2 g1 = __half22float2(*(const __half2*)&ug1.z);
        const float2 g2 = __half22float2(*(const __half2*)&ug2.z);
        const float2 c1 = __half22float2(*(const __half2*)&uc1.z);
        const float2 c2 = __half22float2(*(const __half2*)&uc2.z);
        const float2 hv = __half22float2(*(const __half2*)&uhv.z);
        float sg = 1.f / (1.f + expf(-(c2.x + g1.x)));
        float tau = tb1.x * (0.5f + sg);
        hC.x = hv.x + DT_C * (tanhf(g2.x + c1.x) - hv.x) / tau; tC.x = tau;
        sg = 1.f / (1.f + expf(-(c2.y + g1.y)));
        tau = tb1.y * (0.5f + sg);
        hC.y = hv.y + DT_C * (tanhf(g2.y + c1.y) - hv.y) / tau; tC.y = tau;
        __half2 ph = __float22half2_rn(hC); uout.z = *(uint32_t*)&ph;
    }
    {
        const float2 g1 = __half22float2(*(const __half2*)&ug1.w);
        const float2 g2 = __half22float2(*(const __half2*)&ug2.w);
        const float2 c1 = __half22float2(*(const __half2*)&uc1.w);
        const float2 c2 = __half22float2(*(const __half2*)&uc2.w);
        const float2 hv = __half22float2(*(const __half2*)&uhv.w);
        float sg = 1.f / (1.f + expf(-(c2.x + g1.x)));
        float tau = tb1.z * (0.5f + sg);
        hD.x = hv.x + DT_C * (tanhf(g2.x + c1.x) - hv.x) / tau; tD.x = tau;
        sg = 1.f / (1.f + expf(-(c2.y + g1.y)));
        tau = tb1.w * (0.5f + sg);
        hD.y = hv.y + DT_C * (tanhf(g2.y + c1.y) - hv.y) / tau; tD.y = tau;
        __half2 ph = __float22half2_rn(hD); uout.w = *(uint32_t*)&ph;
    }
#undef LANE2

    *(uint4*)(h16 + idx) = uout;

    if (h_out) {
        *(float4*)(h_out + idx)     = make_float4(hA.x, hA.y, hB.x, hB.y);
        *(float4*)(h_out + idx + 4) = make_float4(hC.x, hC.y, hD.x, hD.y);
    }
    if (tau_out) {
        *(float4*)(tau_out + idx)     = make_float4(tA.x, tA.y, tB.x, tB.y);
        *(float4*)(tau_out + idx + 4) = make_float4(tC.x, tC.y, tD.x, tD.y);
    }
}

// -------------------- launcher --------------------
extern "C" void kernel_launch(void* const* d_in, const int* in_sizes, int n_in,
                              void* d_out, int out_size)
{
    (void)in_sizes; (void)n_in; (void)out_size;

    const float* x           = (const float*)d_in[0];
    const float* hidden      = (const float*)d_in[1];
    const float* W_rec       = (const float*)d_in[2];
    const float* W_in_w      = (const float*)d_in[3];
    const float* W_in_b      = (const float*)d_in[4];
    const float* tau_base    = (const float*)d_in[5];
    const float* tau_adapt_w = (const float*)d_in[6];
    const float* tau_adapt_b = (const float*)d_in[7];

    float* out_h   = (float*)d_out;
    float* out_tau = out_h + (long)B_SZ * H_SZ;

    __half *C1h, *C2h, *G1h, *G2h, *x16, *h16, *Wrec16, *tauh16, *Win16, *taux16;
    cudaGetSymbolAddress((void**)&C1h,    g_C1h);
    cudaGetSymbolAddress((void**)&C2h,    g_C2h);
    cudaGetSymbolAddress((void**)&G1h,    g_G1h);
    cudaGetSymbolAddress((void**)&G2h,    g_G2h);
    cudaGetSymbolAddress((void**)&x16,    g_x16);
    cudaGetSymbolAddress((void**)&h16,    g_h16);
    cudaGetSymbolAddress((void**)&Wrec16, g_Wrec16);
    cudaGetSymbolAddress((void**)&tauh16, g_tauh16);
    cudaGetSymbolAddress((void**)&Win16,  g_Win16);
    cudaGetSymbolAddress((void**)&taux16, g_taux16);

    cudaFuncSetAttribute(gemm_dual_f16, cudaFuncAttributeMaxDynamicSharedMemorySize, SMEM_TOTAL);

    const int ldtau = I_SZ + H_SZ;     // 3072

    // ---- one fused conversion launch ----
    CvtJobs J;
    J.j[0] = {x,                  x16,    B_SZ, I_SZ, I_SZ,  I_SZ};
    J.j[1] = {hidden,             h16,    B_SZ, H_SZ, H_SZ,  H_SZ};
    J.j[2] = {W_rec,              Wrec16, H_SZ, H_SZ, H_SZ,  H_SZ};
    J.j[3] = {tau_adapt_w + I_SZ, tauh16, H_SZ, H_SZ, ldtau, H_SZ};
    J.j[4] = {W_in_w,             Win16,  H_SZ, I_SZ, I_SZ,  I_SZ};
    J.j[5] = {tau_adapt_w,        taux16, H_SZ, I_SZ, ldtau, I_SZ};
    cvt_all_kernel<<<dim3(128, 6), 256>>>(J);

    // ---- merged launch: invariant GEMMs (job0) + step-0 GEMMs (job1) ----
    GemmJob inv  = { x16, I_SZ,
                     Win16,  I_SZ, C1h, W_in_b,
                     taux16, I_SZ, C2h, tau_adapt_b,
                     I_SZ };
    GemmJob loop = { h16, H_SZ,
                     tauh16, H_SZ, G1h, nullptr,
                     Wrec16, H_SZ, G2h, nullptr,
                     H_SZ };

    gemm_dual_f16<<<dim3(32, B_SZ / BM), THREADS, SMEM_TOTAL>>>(inv, loop);

    const int n_ew = (B_SZ * H_SZ) / 8 / 256;   // 4096 blocks
    for (int s = 0; s < NSTEPS; s++) {
        if (s > 0)
            gemm_dual_f16<<<dim3(16, B_SZ / BM), THREADS, SMEM_TOTAL>>>(loop, loop);

        float* ho = (s == NSTEPS - 1) ? out_h   : nullptr;
        float* to = (s == NSTEPS - 1) ? out_tau : nullptr;
        liquid_step_kernel<<<n_ew, 256>>>(h16, G1h, G2h, C1h, C2h, tau_base, ho, to);
    }
}